// round 12
// baseline (speedup 1.0000x reference)
#include <cuda_runtime.h>
#include <cuda_fp16.h>
#include <cstdint>

// Problem constants
#define D_   128
#define K_   1024
#define N_   65536            // B*T = 16*4096
#define DECAY 0.99f
#define EPSV  1e-5f
#define VQ_COMMIT 0.25f
#define REPAIR_THRESH  4e-3f
#define REPAIR2_THRESH 1e-3f

// Output layout (floats), concatenated in reference return order
#define O_Q     0
#define O_DIFF  8388608
#define O_CODE  8388609
#define O_EMB   8454145
#define O_CS    8585217
#define O_MEAN  8586241

// -------- device scratch --------
__device__ float g_embT[K_ * D_];          // embedding transposed [K][D]
__device__ float g_enorm[K_];              // ||e_k||^2
__device__ int   g_code[N_];
__device__ float g_embSumT[K_ * D_];       // per-code x-sum, [K][D]
__device__ float g_diff;
__device__ float g_n;
__device__ int   g_nrepair;
__device__ int   g_repair[N_];
__device__ int   g_hist[K_];
__device__ int   g_offset[K_];
__device__ int   g_cursor[K_];
__device__ int   g_rows[N_];
__device__ int   g_done;
// swizzled fp16 codebook images (hi/lo): 8 tiles of [128 codes][128 dims]
__device__ uint16_t g_EimgHi[K_ * D_];
__device__ uint16_t g_EimgLo[K_ * D_];

// ---------------- helpers ----------------
__device__ __forceinline__ uint32_t smem_u32(const void* p) {
    uint32_t a;
    asm("{ .reg .u64 t; cvta.to.shared.u64 t, %1; cvt.u32.u64 %0, t; }"
        : "=r"(a) : "l"(p));
    return a;
}
__device__ __forceinline__ void ldmx4(uint32_t* r, uint32_t addr) {
    asm volatile("ldmatrix.sync.aligned.m8n8.x4.shared.b16 {%0,%1,%2,%3}, [%4];"
                 : "=r"(r[0]), "=r"(r[1]), "=r"(r[2]), "=r"(r[3]) : "r"(addr));
}
__device__ __forceinline__ void mma16816(float* c, const uint32_t* a,
                                         const uint32_t* b) {
    asm volatile(
        "mma.sync.aligned.m16n8k16.row.col.f32.f16.f16.f32 "
        "{%0,%1,%2,%3}, {%4,%5,%6,%7}, {%8,%9}, {%0,%1,%2,%3};"
        : "+f"(c[0]), "+f"(c[1]), "+f"(c[2]), "+f"(c[3])
        : "r"(a[0]), "r"(a[1]), "r"(a[2]), "r"(a[3]), "r"(b[0]), "r"(b[1]));
}
#define CP16(dst, src) \
    asm volatile("cp.async.ca.shared.global [%0], [%1], 16;" \
                 :: "r"(dst), "l"(src))
#define CP_COMMIT() asm volatile("cp.async.commit_group;" ::: "memory")
#define CP_WAIT0()  asm volatile("cp.async.wait_group 0;" ::: "memory")

__device__ __forceinline__ uint32_t swoff(int r, int ch) {
    return (uint32_t)r * 256u + (uint32_t)((ch ^ (r & 7)) << 4);
}

// merge (b1,b2,i1) with candidate (nb1,nb2,ni)
__device__ __forceinline__ void merge3(float& b1, float& b2, int& i1,
                                       float nb1, float nb2, int ni) {
    if (nb1 < b1 || (nb1 == b1 && ni < i1)) {
        b2 = fminf(b1, nb2);
        b1 = nb1; i1 = ni;
    } else {
        b2 = fminf(b2, nb1);
    }
}

// ============================================================
// 1) enorm
// ============================================================
__global__ void enorm_kernel(const float* __restrict__ E) {
    int k = blockIdx.x * blockDim.x + threadIdx.x;
    if (k >= K_) return;
    float s = 0.0f;
#pragma unroll 8
    for (int d = 0; d < D_; d++) {
        float v = E[d * K_ + k];
        s = fmaf(v, v, s);
    }
    g_enorm[k] = s;
}

// ============================================================
// 2) prep: fp16 hi/lo images + embT + zero sums/counters
// ============================================================
__global__ void prep_kernel(const float* __restrict__ E) {
    int idx = blockIdx.x * blockDim.x + threadIdx.x;   // 131072 = K_*D_
    int k = idx & (K_ - 1);
    int d = idx >> 10;
    float v = E[d * K_ + k];
    __half h = __float2half_rn(v);
    __half l = __float2half_rn(v - __half2float(h));
    int tile = k >> 7, r = k & 127;
    int pos = tile * 16384 + r * 128 + (((d >> 3) ^ (r & 7)) << 3) + (d & 7);
    g_EimgHi[pos] = __half_as_ushort(h);
    g_EimgLo[pos] = __half_as_ushort(l);
    g_embT[k * D_ + d] = v;
    g_embSumT[idx] = 0.0f;
    if (idx < K_) g_hist[idx] = 0;
    if (idx == 0) { g_diff = 0.0f; g_nrepair = 0; g_done = 0; }
}

// ============================================================
// 3) argmin via mma.sync fp16 3-term split GEMM (+ hist count)
// ============================================================
#define SM_XH   0
#define SM_XL   32768
#define SM_E0   65536
#define SM_E1   131072
#define SM_ENS  196608
#define SM_CAND 200704
#define SM_ARG_TOTAL (200704 + 6144)

__device__ __forceinline__ void cp_tile(uint32_t dst, int tile, int tid) {
    const char* srcH = (const char*)g_EimgHi + (size_t)tile * 32768;
    const char* srcL = (const char*)g_EimgLo + (size_t)tile * 32768;
#pragma unroll
    for (int i = 0; i < 8; i++) {
        CP16(dst + tid * 16 + i * 4096, srcH + tid * 16 + i * 4096);
        CP16(dst + 32768 + tid * 16 + i * 4096, srcL + tid * 16 + i * 4096);
    }
}

__global__ __launch_bounds__(256, 1)
void argmin_mma_kernel(const float* __restrict__ in, float* __restrict__ out_code) {
    extern __shared__ char smem[];
    const uint32_t sb = smem_u32(smem);
    const int tid = threadIdx.x;
    const int lane = tid & 31;
    const int wid = tid >> 5;
    const int warp_m = wid & 1;      // 2 x m64
    const int warp_q = wid >> 1;     // 4 x n32
    const int row0 = blockIdx.x * 128;

    cp_tile(sb + SM_E0, 0, tid);
    CP_COMMIT();

    float* ens = (float*)(smem + SM_ENS);
#pragma unroll
    for (int i = 0; i < 4; i++) ens[tid + i * 256] = g_enorm[tid + i * 256];

    // build X hi/lo fp16 swizzled images
    {
        const int s = tid & 63;          // dim-pair
        const int rh = tid >> 6;         // row quarter
        const float2* gin = (const float2*)in;
#pragma unroll 4
        for (int rr = 0; rr < 32; rr++) {
            int r = rh * 32 + rr;
            float2 x = gin[(size_t)(row0 + r) * 64 + s];
            __half h0 = __float2half_rn(x.x);
            __half h1 = __float2half_rn(x.y);
            __half l0 = __float2half_rn(x.x - __half2float(h0));
            __half l1 = __float2half_rn(x.y - __half2float(h1));
            uint32_t off = (uint32_t)r * 256u +
                           (uint32_t)((((s >> 2) ^ (r & 7)) << 4) + (s & 3) * 4);
            *(uint32_t*)(smem + SM_XH + off) =
                (uint32_t)__half_as_ushort(h0) | ((uint32_t)__half_as_ushort(h1) << 16);
            *(uint32_t*)(smem + SM_XL + off) =
                (uint32_t)__half_as_ushort(l0) | ((uint32_t)__half_as_ushort(l1) << 16);
        }
    }

    const int a_row = lane & 15;
    const int a_ksel = lane >> 4;
    const int b_n = (lane & 7) + ((lane & 16) >> 1);
    const int b_ksel = (lane >> 3) & 1;

    float best[4][2], best2[4][2];
    int bidx[4][2];
#pragma unroll
    for (int mt = 0; mt < 4; mt++)
#pragma unroll
        for (int h = 0; h < 2; h++) {
            best[mt][h] = 3.4e38f; best2[mt][h] = 3.4e38f; bidx[mt][h] = 0;
        }

    for (int nt = 0; nt < 8; nt++) {
        CP_WAIT0();
        __syncthreads();
        if (nt < 7) { cp_tile(sb + (((nt + 1) & 1) ? SM_E1 : SM_E0), nt + 1, tid); CP_COMMIT(); }
        const uint32_t ebh = sb + ((nt & 1) ? SM_E1 : SM_E0);
        const uint32_t ebl = ebh + 32768;

        float acc[4][4][4];
#pragma unroll
        for (int mt = 0; mt < 4; mt++)
#pragma unroll
            for (int nn = 0; nn < 4; nn++)
#pragma unroll
                for (int i = 0; i < 4; i++) acc[mt][nn][i] = 0.0f;

#pragma unroll
        for (int kc = 0; kc < 8; kc++) {
            uint32_t Ah[4][4], Al[4][4];
#pragma unroll
            for (int mt = 0; mt < 4; mt++) {
                int r = warp_m * 64 + mt * 16 + a_row;
                uint32_t off = swoff(r, 2 * kc + a_ksel);
                ldmx4(Ah[mt], sb + SM_XH + off);
                ldmx4(Al[mt], sb + SM_XL + off);
            }
#pragma unroll
            for (int g = 0; g < 2; g++) {
                int n = warp_q * 32 + g * 16 + b_n;
                uint32_t off = swoff(n, 2 * kc + b_ksel);
                uint32_t Bh[4], Bl[4];
                ldmx4(Bh, ebh + off);
                ldmx4(Bl, ebl + off);
#pragma unroll
                for (int mt = 0; mt < 4; mt++) {
                    mma16816(acc[mt][2 * g],     Ah[mt], Bh);
                    mma16816(acc[mt][2 * g + 1], Ah[mt], Bh + 2);
                    mma16816(acc[mt][2 * g],     Al[mt], Bh);
                    mma16816(acc[mt][2 * g + 1], Al[mt], Bh + 2);
                    mma16816(acc[mt][2 * g],     Ah[mt], Bl);
                    mma16816(acc[mt][2 * g + 1], Ah[mt], Bl + 2);
                }
            }
        }

        const int cbase = nt * 128 + warp_q * 32 + (lane & 3) * 2;
#pragma unroll
        for (int mt = 0; mt < 4; mt++)
#pragma unroll
            for (int nn = 0; nn < 4; nn++)
#pragma unroll
                for (int i = 0; i < 4; i++) {
                    int c = cbase + nn * 8 + (i & 1);
                    int h = i >> 1;
                    float dist = fmaf(-2.0f, acc[mt][nn][i], ens[c]);
                    if (dist < best[mt][h]) {
                        best2[mt][h] = best[mt][h];
                        best[mt][h] = dist; bidx[mt][h] = c;
                    } else {
                        best2[mt][h] = fminf(best2[mt][h], dist);
                    }
                }
    }

    float* cb  = (float*)(smem + SM_CAND);          // [4][128]
    float* cb2 = (float*)(smem + SM_CAND + 2048);
    int*   ci  = (int*)(smem + SM_CAND + 4096);
#pragma unroll
    for (int mt = 0; mt < 4; mt++)
#pragma unroll
        for (int h = 0; h < 2; h++) {
            float b1 = best[mt][h], b2 = best2[mt][h];
            int i1 = bidx[mt][h];
#pragma unroll
            for (int off = 1; off <= 2; off <<= 1) {
                float ob1 = __shfl_xor_sync(0xffffffffu, b1, off);
                int   oi1 = __shfl_xor_sync(0xffffffffu, i1, off);
                float ob2 = __shfl_xor_sync(0xffffffffu, b2, off);
                merge3(b1, b2, i1, ob1, ob2, oi1);
            }
            if ((lane & 3) == 0) {
                int lrow = warp_m * 64 + mt * 16 + (lane >> 2) + 8 * h;
                cb[warp_q * 128 + lrow] = b1;
                cb2[warp_q * 128 + lrow] = b2;
                ci[warp_q * 128 + lrow] = i1;
            }
        }
    __syncthreads();

    if (tid < 128) {
        float fb = cb[tid], fs = cb2[tid];
        int fi = ci[tid];
#pragma unroll
        for (int q = 1; q < 4; q++)
            merge3(fb, fs, fi, cb[q * 128 + tid], cb2[q * 128 + tid],
                   ci[q * 128 + tid]);
        int row = row0 + tid;
        g_code[row] = fi;
        out_code[row] = (float)fi;
        atomicAdd(&g_hist[fi], 1);
        if (fs - fb < REPAIR_THRESH) {
            int slot = atomicAdd(&g_nrepair, 1);
            if (slot < N_) g_repair[slot] = row;
        }
    }
}

// ============================================================
// 4) repair: fp32 warp-per-row re-rank; fp64 ultra-ties are
//    BLOCK-collective with 4-way ILP chains.
//    Last block scans hist + computes n.
// ============================================================
#define RGROUP 8
__global__ __launch_bounds__(256)
void repair_kernel(const float* __restrict__ in,
                   const float* __restrict__ E,
                   const float* __restrict__ cs_in,
                   float* __restrict__ out_code) {
    __shared__ float xs[RGROUP][D_];
    __shared__ int rows_s[RGROUP];
    __shared__ float cb1[RGROUP][256];
    __shared__ float cb2s[RGROUP][256];
    __shared__ int   cbi[RGROUP][256];
    __shared__ int ultra_list[RGROUP];
    __shared__ int nultra;
    __shared__ double dmin[256];
    __shared__ int dmini[256];
    __shared__ int bsum[256];
    __shared__ int amlast;
    const int tid = threadIdx.x;
    const int lane = tid & 31;
    const int wid = tid >> 5;
    int nrep = g_nrepair;
    if (nrep > N_) nrep = N_;

    for (int base = blockIdx.x * RGROUP; base < nrep; base += gridDim.x * RGROUP) {
        int nr = nrep - base; if (nr > RGROUP) nr = RGROUP;
        if (tid < nr) rows_s[tid] = g_repair[base + tid];
        if (tid == 0) nultra = 0;
        __syncthreads();
        for (int j = tid; j < nr * D_; j += 256)
            xs[j >> 7][j & 127] = in[(size_t)rows_s[j >> 7] * D_ + (j & 127)];
        __syncthreads();

        float best[RGROUP], best2[RGROUP]; int bidx[RGROUP];
#pragma unroll
        for (int r = 0; r < RGROUP; r++) {
            best[r] = 3.4e38f; best2[r] = 3.4e38f; bidx[r] = 0;
        }

#pragma unroll
        for (int kk = 0; kk < 4; kk++) {
            int k = tid + kk * 256;
            float s[RGROUP];
#pragma unroll
            for (int r = 0; r < RGROUP; r++) s[r] = 0.0f;
#pragma unroll 4
            for (int d = 0; d < D_; d += 2) {
                float e0 = E[d * K_ + k];
                float e1 = E[(d + 1) * K_ + k];
#pragma unroll
                for (int r = 0; r < RGROUP; r++) {
                    float d0 = xs[r][d] - e0;
                    float d1 = xs[r][d + 1] - e1;
                    s[r] = fmaf(d0, d0, s[r]);
                    s[r] = fmaf(d1, d1, s[r]);
                }
            }
#pragma unroll
            for (int r = 0; r < RGROUP; r++) {
                if (s[r] < best[r]) { best2[r] = best[r]; best[r] = s[r]; bidx[r] = k; }
                else best2[r] = fminf(best2[r], s[r]);
            }
        }
#pragma unroll
        for (int r = 0; r < RGROUP; r++) {
            cb1[r][tid] = best[r];
            cb2s[r][tid] = best2[r];
            cbi[r][tid] = bidx[r];
        }
        __syncthreads();

        // warp wid merges row wid's candidates
        if (wid < nr) {
            float b1 = 3.4e38f, b2 = 3.4e38f; int i1 = 0;
#pragma unroll
            for (int i = 0; i < 8; i++)
                merge3(b1, b2, i1, cb1[wid][lane + 32 * i],
                       cb2s[wid][lane + 32 * i], cbi[wid][lane + 32 * i]);
#pragma unroll
            for (int off = 16; off > 0; off >>= 1) {
                float ob1 = __shfl_down_sync(0xffffffffu, b1, off);
                float ob2 = __shfl_down_sync(0xffffffffu, b2, off);
                int   oi1 = __shfl_down_sync(0xffffffffu, i1, off);
                merge3(b1, b2, i1, ob1, ob2, oi1);
            }
            if (lane == 0) {
                if (b2 - b1 < REPAIR2_THRESH) {
                    ultra_list[atomicAdd(&nultra, 1)] = wid;
                } else {
                    int row = rows_s[wid];
                    int oldc = g_code[row];
                    if (i1 != oldc) {
                        atomicSub(&g_hist[oldc], 1);
                        atomicAdd(&g_hist[i1], 1);
                        g_code[row] = i1;
                        out_code[row] = (float)i1;
                    }
                }
            }
        }
        __syncthreads();

        // BLOCK-collective fp64 exact pass: 4 codes/thread, 4-way ILP
        int nu = nultra;
        for (int u = 0; u < nu; u++) {
            int r = ultra_list[u];
            double db = 1e300; int dbi = 0;
#pragma unroll
            for (int kk = 0; kk < 4; kk++) {
                int k = tid + kk * 256;
                double s0 = 0.0, s1 = 0.0, s2 = 0.0, s3 = 0.0;
#pragma unroll 2
                for (int d = 0; d < D_; d += 4) {
                    double f0 = (double)xs[r][d]     - (double)E[d * K_ + k];
                    double f1 = (double)xs[r][d + 1] - (double)E[(d + 1) * K_ + k];
                    double f2 = (double)xs[r][d + 2] - (double)E[(d + 2) * K_ + k];
                    double f3 = (double)xs[r][d + 3] - (double)E[(d + 3) * K_ + k];
                    s0 = fma(f0, f0, s0);
                    s1 = fma(f1, f1, s1);
                    s2 = fma(f2, f2, s2);
                    s3 = fma(f3, f3, s3);
                }
                double s = (s0 + s1) + (s2 + s3);
                if (s < db || (s == db && k < dbi)) { db = s; dbi = k; }
            }
            dmin[tid] = db; dmini[tid] = dbi;
            __syncthreads();
            for (int off = 128; off > 0; off >>= 1) {
                if (tid < off) {
                    double od = dmin[tid + off];
                    int oi = dmini[tid + off];
                    if (od < dmin[tid] || (od == dmin[tid] && oi < dmini[tid])) {
                        dmin[tid] = od; dmini[tid] = oi;
                    }
                }
                __syncthreads();
            }
            if (tid == 0) {
                int row = rows_s[r];
                int oldc = g_code[row];
                int newc = dmini[0];
                if (newc != oldc) {
                    atomicSub(&g_hist[oldc], 1);
                    atomicAdd(&g_hist[newc], 1);
                    g_code[row] = newc;
                    out_code[row] = (float)newc;
                }
            }
            __syncthreads();
        }
    }

    // ---- last-block ticket: scan hist + compute n ----
    __threadfence();
    if (tid == 0) amlast = (atomicAdd(&g_done, 1) == gridDim.x - 1) ? 1 : 0;
    __syncthreads();
    if (!amlast) return;

    int b0 = g_hist[tid * 4 + 0];
    int b1 = g_hist[tid * 4 + 1];
    int b2 = g_hist[tid * 4 + 2];
    int b3 = g_hist[tid * 4 + 3];
    bsum[tid] = b0 + b1 + b2 + b3;
    __syncthreads();
    for (int off = 1; off < 256; off <<= 1) {
        int v = (tid >= off) ? bsum[tid - off] : 0;
        __syncthreads();
        bsum[tid] += v;
        __syncthreads();
    }
    int excl = bsum[tid] - (b0 + b1 + b2 + b3);
    g_offset[tid * 4 + 0] = excl;
    g_offset[tid * 4 + 1] = excl + b0;
    g_offset[tid * 4 + 2] = excl + b0 + b1;
    g_offset[tid * 4 + 3] = excl + b0 + b1 + b2;
    g_cursor[tid * 4 + 0] = excl;
    g_cursor[tid * 4 + 1] = excl + b0;
    g_cursor[tid * 4 + 2] = excl + b0 + b1;
    g_cursor[tid * 4 + 3] = excl + b0 + b1 + b2;

    float cs = cs_in[tid * 4] + cs_in[tid * 4 + 1] + cs_in[tid * 4 + 2] +
               cs_in[tid * 4 + 3];
    cb1[0][tid] = cs;
    __syncthreads();
    for (int off = 128; off > 0; off >>= 1) {
        if (tid < off) cb1[0][tid] += cb1[0][tid + off];
        __syncthreads();
    }
    if (tid == 0) g_n = DECAY * cb1[0][0] + (1.0f - DECAY) * (float)N_;
}

// ============================================================
// 5) scatter rows by code
// ============================================================
__global__ void scatter_kernel() {
    int row = blockIdx.x * 1024 + threadIdx.x;
    int c = g_code[row];
    int p = atomicAdd(&g_cursor[c], 1);
    g_rows[p] = row;
}

// ============================================================
// 6) segsum CHUNKED: 1024 blocks x 64 sorted rows each.
// ============================================================
#define CHUNK 64
__global__ __launch_bounds__(128)
void segsum_kernel(const float* __restrict__ in, float* __restrict__ out_q) {
    __shared__ int srow[CHUNK], scode[CHUNK];
    __shared__ float red[128];
    const int t = threadIdx.x;
    const int i0 = blockIdx.x * CHUNK;

    if (t < CHUNK) {
        int r = g_rows[i0 + t];
        srow[t] = r;
        scode[t] = g_code[r];
    }
    __syncthreads();

    float s = 0.0f, dsum = 0.0f;
    int cur = scode[0];
    float ek = g_embT[cur * D_ + t];

    for (int i = 0; i < CHUNK; i++) {
        int c = scode[i];
        if (c != cur) {
            atomicAdd(&g_embSumT[cur * D_ + t], s);
            s = 0.0f;
            cur = c;
            ek = g_embT[cur * D_ + t];
        }
        int row = srow[i];
        float x = in[(size_t)row * D_ + t];
        s += x;
        float df = x - ek;
        dsum = fmaf(df, df, dsum);
        out_q[(size_t)row * D_ + t] = ek;
    }
    atomicAdd(&g_embSumT[cur * D_ + t], s);

    red[t] = dsum;
    __syncthreads();
    for (int off = 64; off > 0; off >>= 1) {
        if (t < off) red[t] += red[t + off];
        __syncthreads();
    }
    if (t == 0) atomicAdd(&g_diff, red[0]);
}

// ============================================================
// 7) finalize: O_CS, O_DIFF, O_MEAN, O_EMB
// ============================================================
__global__ void finalize_kernel(const float* __restrict__ cs_in,
                                const float* __restrict__ mean_in,
                                float* __restrict__ out) {
    int idx = blockIdx.x * blockDim.x + threadIdx.x;
    if (idx < K_)
        out[O_CS + idx] = cs_in[idx] * DECAY + (1.0f - DECAY) * (float)g_hist[idx];
    if (idx == 0)
        out[O_DIFF] = VQ_COMMIT * g_diff / (float)(N_ * D_);
    if (idx >= D_ * K_) return;
    int d = idx >> 10;
    int k = idx & (K_ - 1);
    float em = mean_in[idx] * DECAY + (1.0f - DECAY) * g_embSumT[k * D_ + d];
    out[O_MEAN + idx] = em;
    float n = g_n;
    float ncs = cs_in[k] * DECAY + (1.0f - DECAY) * (float)g_hist[k];
    float cs = (ncs + EPSV) / (n + K_ * EPSV) * n;
    out[O_EMB + idx] = em / cs;
}

// ============================================================
extern "C" void kernel_launch(void* const* d_in, const int* in_sizes, int n_in,
                              void* d_out, int out_size) {
    const float* in      = (const float*)d_in[0];  // [B,T,D]
    const float* emb     = (const float*)d_in[1];  // [D,K]
    const float* cs_in   = (const float*)d_in[2];  // [K]
    const float* mean_in = (const float*)d_in[3];  // [D,K]
    float* out = (float*)d_out;

    static bool attr_set = false;
    if (!attr_set) {
        cudaFuncSetAttribute(argmin_mma_kernel,
                             cudaFuncAttributeMaxDynamicSharedMemorySize,
                             SM_ARG_TOTAL);
        attr_set = true;
    }

    enorm_kernel<<<K_ / 256, 256>>>(emb);                                  // 1
    prep_kernel<<<(K_ * D_) / 256, 256>>>(emb);                            // 2
    argmin_mma_kernel<<<N_ / 128, 256, SM_ARG_TOTAL>>>(in, out + O_CODE);  // 3
    repair_kernel<<<256, 256>>>(in, emb, cs_in, out + O_CODE);             // 4 (ncu slot)
    scatter_kernel<<<N_ / 1024, 1024>>>();                                 // 5
    segsum_kernel<<<N_ / CHUNK, 128>>>(in, out + O_Q);                     // 6
    finalize_kernel<<<(D_ * K_ + 255) / 256, 256>>>(cs_in, mean_in, out);  // 7
}

// round 13
// speedup vs baseline: 3.6062x; 3.6062x over previous
#include <cuda_runtime.h>
#include <cuda_fp16.h>
#include <cstdint>

// Problem constants
#define D_   128
#define K_   1024
#define N_   65536            // B*T = 16*4096
#define DECAY 0.99f
#define EPSV  1e-5f
#define VQ_COMMIT 0.25f
#define REPAIR_THRESH  0.04f
#define CAND_MARGIN    2e-3f
#define MAXCAND 32

// Output layout (floats), concatenated in reference return order
#define O_Q     0
#define O_DIFF  8388608
#define O_CODE  8388609
#define O_EMB   8454145
#define O_CS    8585217
#define O_MEAN  8586241

// -------- device scratch --------
__device__ float g_embT[K_ * D_];          // embedding transposed [K][D]
__device__ float g_enorm[K_];              // ||e_k||^2
__device__ int   g_code[N_];
__device__ float g_embSumT[K_ * D_];       // per-code x-sum, [K][D]
__device__ float g_diff;
__device__ float g_n;
__device__ int   g_nrepair;
__device__ int   g_repair[N_];
__device__ int   g_hist[K_];
__device__ int   g_offset[K_];
__device__ int   g_cursor[K_];
__device__ int   g_rows[N_];
__device__ int   g_done;
// swizzled fp16 codebook image: 8 tiles of [128 codes][128 dims]
__device__ uint16_t g_Eimg[K_ * D_];

// ---------------- helpers ----------------
__device__ __forceinline__ uint32_t smem_u32(const void* p) {
    uint32_t a;
    asm("{ .reg .u64 t; cvta.to.shared.u64 t, %1; cvt.u32.u64 %0, t; }"
        : "=r"(a) : "l"(p));
    return a;
}
__device__ __forceinline__ void ldmx4(uint32_t* r, uint32_t addr) {
    asm volatile("ldmatrix.sync.aligned.m8n8.x4.shared.b16 {%0,%1,%2,%3}, [%4];"
                 : "=r"(r[0]), "=r"(r[1]), "=r"(r[2]), "=r"(r[3]) : "r"(addr));
}
__device__ __forceinline__ void mma16816(float* c, const uint32_t* a,
                                         const uint32_t* b) {
    asm volatile(
        "mma.sync.aligned.m16n8k16.row.col.f32.f16.f16.f32 "
        "{%0,%1,%2,%3}, {%4,%5,%6,%7}, {%8,%9}, {%0,%1,%2,%3};"
        : "+f"(c[0]), "+f"(c[1]), "+f"(c[2]), "+f"(c[3])
        : "r"(a[0]), "r"(a[1]), "r"(a[2]), "r"(a[3]), "r"(b[0]), "r"(b[1]));
}
#define CP16(dst, src) \
    asm volatile("cp.async.ca.shared.global [%0], [%1], 16;" \
                 :: "r"(dst), "l"(src))
#define CP_COMMIT() asm volatile("cp.async.commit_group;" ::: "memory")
#define CP_WAIT0()  asm volatile("cp.async.wait_group 0;" ::: "memory")

__device__ __forceinline__ uint32_t swoff(int r, int ch) {
    return (uint32_t)r * 256u + (uint32_t)((ch ^ (r & 7)) << 4);
}

// merge (b1,b2,i1) with candidate (nb1,nb2,ni)
__device__ __forceinline__ void merge3(float& b1, float& b2, int& i1,
                                       float nb1, float nb2, int ni) {
    if (nb1 < b1 || (nb1 == b1 && ni < i1)) {
        b2 = fminf(b1, nb2);
        b1 = nb1; i1 = ni;
    } else {
        b2 = fminf(b2, nb1);
    }
}

// ============================================================
// 1) enorm
// ============================================================
__global__ void enorm_kernel(const float* __restrict__ E) {
    int k = blockIdx.x * blockDim.x + threadIdx.x;
    if (k >= K_) return;
    float s = 0.0f;
#pragma unroll 8
    for (int d = 0; d < D_; d++) {
        float v = E[d * K_ + k];
        s = fmaf(v, v, s);
    }
    g_enorm[k] = s;
}

// ============================================================
// 2) prep: fp16 image + embT + zero sums/counters
// ============================================================
__global__ void prep_kernel(const float* __restrict__ E) {
    int idx = blockIdx.x * blockDim.x + threadIdx.x;   // 131072 = K_*D_
    int k = idx & (K_ - 1);
    int d = idx >> 10;
    float v = E[d * K_ + k];
    __half h = __float2half_rn(v);
    int tile = k >> 7, r = k & 127;
    g_Eimg[tile * 16384 + r * 128 + (((d >> 3) ^ (r & 7)) << 3) + (d & 7)] =
        __half_as_ushort(h);
    g_embT[k * D_ + d] = v;
    g_embSumT[idx] = 0.0f;
    if (idx < K_) g_hist[idx] = 0;
    if (idx == 0) { g_diff = 0.0f; g_nrepair = 0; g_done = 0; }
}

// ============================================================
// 3) argmin via mma.sync fp16 2-term split GEMM (+ hist count)
// ============================================================
#define SM_XH   0
#define SM_XL   32768
#define SM_E0   65536
#define SM_E1   98304
#define SM_ENS  131072
#define SM_CAND 135168
#define SM_ARG_TOTAL (135168 + 6144)

__device__ __forceinline__ void cp_tile(uint32_t dst, int tile, int tid) {
    const char* src = (const char*)g_Eimg + (size_t)tile * 32768;
#pragma unroll
    for (int i = 0; i < 8; i++)
        CP16(dst + tid * 16 + i * 4096, src + tid * 16 + i * 4096);
}

__global__ __launch_bounds__(256, 1)
void argmin_mma_kernel(const float* __restrict__ in, float* __restrict__ out_code) {
    extern __shared__ char smem[];
    const uint32_t sb = smem_u32(smem);
    const int tid = threadIdx.x;
    const int lane = tid & 31;
    const int wid = tid >> 5;
    const int warp_m = wid & 1;      // 2 x m64
    const int warp_q = wid >> 1;     // 4 x n32
    const int row0 = blockIdx.x * 128;

    cp_tile(sb + SM_E0, 0, tid);
    CP_COMMIT();

    float* ens = (float*)(smem + SM_ENS);
#pragma unroll
    for (int i = 0; i < 4; i++) ens[tid + i * 256] = g_enorm[tid + i * 256];

    // build X hi/lo fp16 swizzled images
    {
        const int s = tid & 63;          // dim-pair
        const int rh = tid >> 6;         // row quarter
        const float2* gin = (const float2*)in;
#pragma unroll 4
        for (int rr = 0; rr < 32; rr++) {
            int r = rh * 32 + rr;
            float2 x = gin[(size_t)(row0 + r) * 64 + s];
            __half h0 = __float2half_rn(x.x);
            __half h1 = __float2half_rn(x.y);
            __half l0 = __float2half_rn(x.x - __half2float(h0));
            __half l1 = __float2half_rn(x.y - __half2float(h1));
            uint32_t off = (uint32_t)r * 256u +
                           (uint32_t)((((s >> 2) ^ (r & 7)) << 4) + (s & 3) * 4);
            *(uint32_t*)(smem + SM_XH + off) =
                (uint32_t)__half_as_ushort(h0) | ((uint32_t)__half_as_ushort(h1) << 16);
            *(uint32_t*)(smem + SM_XL + off) =
                (uint32_t)__half_as_ushort(l0) | ((uint32_t)__half_as_ushort(l1) << 16);
        }
    }

    const int a_row = lane & 15;
    const int a_ksel = lane >> 4;
    const int b_n = (lane & 7) + ((lane & 16) >> 1);
    const int b_ksel = (lane >> 3) & 1;

    float best[4][2], best2[4][2];
    int bidx[4][2];
#pragma unroll
    for (int mt = 0; mt < 4; mt++)
#pragma unroll
        for (int h = 0; h < 2; h++) {
            best[mt][h] = 3.4e38f; best2[mt][h] = 3.4e38f; bidx[mt][h] = 0;
        }

    for (int nt = 0; nt < 8; nt++) {
        CP_WAIT0();
        __syncthreads();
        if (nt < 7) { cp_tile(sb + (((nt + 1) & 1) ? SM_E1 : SM_E0), nt + 1, tid); CP_COMMIT(); }
        const uint32_t eb = sb + ((nt & 1) ? SM_E1 : SM_E0);

        float acc[4][4][4];
#pragma unroll
        for (int mt = 0; mt < 4; mt++)
#pragma unroll
            for (int nn = 0; nn < 4; nn++)
#pragma unroll
                for (int i = 0; i < 4; i++) acc[mt][nn][i] = 0.0f;

#pragma unroll
        for (int kc = 0; kc < 8; kc++) {
            uint32_t Ah[4][4], Al[4][4];
#pragma unroll
            for (int mt = 0; mt < 4; mt++) {
                int r = warp_m * 64 + mt * 16 + a_row;
                uint32_t off = swoff(r, 2 * kc + a_ksel);
                ldmx4(Ah[mt], sb + SM_XH + off);
                ldmx4(Al[mt], sb + SM_XL + off);
            }
#pragma unroll
            for (int g = 0; g < 2; g++) {
                int n = warp_q * 32 + g * 16 + b_n;
                uint32_t off = swoff(n, 2 * kc + b_ksel);
                uint32_t Bh[4];
                ldmx4(Bh, eb + off);
#pragma unroll
                for (int mt = 0; mt < 4; mt++) {
                    mma16816(acc[mt][2 * g],     Ah[mt], Bh);
                    mma16816(acc[mt][2 * g + 1], Ah[mt], Bh + 2);
                    mma16816(acc[mt][2 * g],     Al[mt], Bh);
                    mma16816(acc[mt][2 * g + 1], Al[mt], Bh + 2);
                }
            }
        }

        const int cbase = nt * 128 + warp_q * 32 + (lane & 3) * 2;
#pragma unroll
        for (int mt = 0; mt < 4; mt++)
#pragma unroll
            for (int nn = 0; nn < 4; nn++)
#pragma unroll
                for (int i = 0; i < 4; i++) {
                    int c = cbase + nn * 8 + (i & 1);
                    int h = i >> 1;
                    float dist = fmaf(-2.0f, acc[mt][nn][i], ens[c]);
                    if (dist < best[mt][h]) {
                        best2[mt][h] = best[mt][h];
                        best[mt][h] = dist; bidx[mt][h] = c;
                    } else {
                        best2[mt][h] = fminf(best2[mt][h], dist);
                    }
                }
    }

    float* cb  = (float*)(smem + SM_CAND);          // [4][128]
    float* cb2 = (float*)(smem + SM_CAND + 2048);
    int*   ci  = (int*)(smem + SM_CAND + 4096);
#pragma unroll
    for (int mt = 0; mt < 4; mt++)
#pragma unroll
        for (int h = 0; h < 2; h++) {
            float b1 = best[mt][h], b2 = best2[mt][h];
            int i1 = bidx[mt][h];
#pragma unroll
            for (int off = 1; off <= 2; off <<= 1) {
                float ob1 = __shfl_xor_sync(0xffffffffu, b1, off);
                int   oi1 = __shfl_xor_sync(0xffffffffu, i1, off);
                float ob2 = __shfl_xor_sync(0xffffffffu, b2, off);
                merge3(b1, b2, i1, ob1, ob2, oi1);
            }
            if ((lane & 3) == 0) {
                int lrow = warp_m * 64 + mt * 16 + (lane >> 2) + 8 * h;
                cb[warp_q * 128 + lrow] = b1;
                cb2[warp_q * 128 + lrow] = b2;
                ci[warp_q * 128 + lrow] = i1;
            }
        }
    __syncthreads();

    if (tid < 128) {
        float fb = cb[tid], fs = cb2[tid];
        int fi = ci[tid];
#pragma unroll
        for (int q = 1; q < 4; q++)
            merge3(fb, fs, fi, cb[q * 128 + tid], cb2[q * 128 + tid],
                   ci[q * 128 + tid]);
        int row = row0 + tid;
        g_code[row] = fi;
        out_code[row] = (float)fi;
        atomicAdd(&g_hist[fi], 1);
        if (fs - fb < REPAIR_THRESH) {
            int slot = atomicAdd(&g_nrepair, 1);
            if (slot < N_) g_repair[slot] = row;
        }
    }
}

// ============================================================
// 4) repair: fp32 full re-rank with dist matrix in smem;
//    fp64 only on candidates within CAND_MARGIN of the min.
//    Last block scans hist + computes n.
// ============================================================
#define RGROUP 8
__global__ __launch_bounds__(256)
void repair_kernel(const float* __restrict__ in,
                   const float* __restrict__ E,
                   const float* __restrict__ cs_in,
                   float* __restrict__ out_code) {
    __shared__ float dists[RGROUP][K_];   // 32 KB
    __shared__ float xs[RGROUP][D_];      // 4 KB
    __shared__ int rows_s[RGROUP];
    __shared__ float rmin[256];
    __shared__ int rmini[256];
    __shared__ int cand_k[MAXCAND];
    __shared__ double cand_d[MAXCAND];
    __shared__ int ncand;
    __shared__ int bsum[256];
    __shared__ int amlast;
    const int tid = threadIdx.x;
    int nrep = g_nrepair;
    if (nrep > N_) nrep = N_;

    for (int base = blockIdx.x * RGROUP; base < nrep; base += gridDim.x * RGROUP) {
        int nr = nrep - base; if (nr > RGROUP) nr = RGROUP;
        if (tid < nr) rows_s[tid] = g_repair[base + tid];
        __syncthreads();
        for (int j = tid; j < nr * D_; j += 256)
            xs[j >> 7][j & 127] = in[(size_t)rows_s[j >> 7] * D_ + (j & 127)];
        __syncthreads();

        // fp32 exact-form distances for all 1024 codes
#pragma unroll
        for (int kk = 0; kk < 4; kk++) {
            int k = tid + kk * 256;
            float s[RGROUP];
#pragma unroll
            for (int r = 0; r < RGROUP; r++) s[r] = 0.0f;
#pragma unroll 4
            for (int d = 0; d < D_; d += 2) {
                float e0 = E[d * K_ + k];
                float e1 = E[(d + 1) * K_ + k];
#pragma unroll
                for (int r = 0; r < RGROUP; r++) {
                    float d0 = xs[r][d] - e0;
                    float d1 = xs[r][d + 1] - e1;
                    s[r] = fmaf(d0, d0, s[r]);
                    s[r] = fmaf(d1, d1, s[r]);
                }
            }
#pragma unroll
            for (int r = 0; r < RGROUP; r++) dists[r][k] = s[r];
        }
        __syncthreads();

        for (int r = 0; r < nr; r++) {
            // block argmin over dists[r][*]
            float b = 3.4e38f; int bi = 0;
#pragma unroll
            for (int kk = 0; kk < 4; kk++) {
                int k = tid + kk * 256;
                float v = dists[r][k];
                if (v < b || (v == b && k < bi)) { b = v; bi = k; }
            }
            rmin[tid] = b; rmini[tid] = bi;
            if (tid == 0) ncand = 0;
            __syncthreads();
            for (int off = 128; off > 0; off >>= 1) {
                if (tid < off) {
                    float ob = rmin[tid + off];
                    int oi = rmini[tid + off];
                    if (ob < rmin[tid] || (ob == rmin[tid] && oi < rmini[tid])) {
                        rmin[tid] = ob; rmini[tid] = oi;
                    }
                }
                __syncthreads();
            }
            float m = rmin[0];
            int mi = rmini[0];
            __syncthreads();

            // gather candidates within margin
#pragma unroll
            for (int kk = 0; kk < 4; kk++) {
                int k = tid + kk * 256;
                if (dists[r][k] < m + CAND_MARGIN) {
                    int p = atomicAdd(&ncand, 1);
                    if (p < MAXCAND) cand_k[p] = k;
                }
            }
            __syncthreads();
            int nc = ncand;

            if (nc > 1 && nc <= MAXCAND) {
                // fp64 exact on candidates (one thread each, 4-way ILP)
                if (tid < nc) {
                    int k = cand_k[tid];
                    double s0 = 0.0, s1 = 0.0, s2 = 0.0, s3 = 0.0;
#pragma unroll 2
                    for (int d = 0; d < D_; d += 4) {
                        double f0 = (double)xs[r][d]     - (double)E[d * K_ + k];
                        double f1 = (double)xs[r][d + 1] - (double)E[(d + 1) * K_ + k];
                        double f2 = (double)xs[r][d + 2] - (double)E[(d + 2) * K_ + k];
                        double f3 = (double)xs[r][d + 3] - (double)E[(d + 3) * K_ + k];
                        s0 = fma(f0, f0, s0);
                        s1 = fma(f1, f1, s1);
                        s2 = fma(f2, f2, s2);
                        s3 = fma(f3, f3, s3);
                    }
                    cand_d[tid] = (s0 + s1) + (s2 + s3);
                }
                __syncthreads();
                if (tid == 0) {
                    double bd = 1e300; int bk = 1 << 30;
                    for (int i = 0; i < nc; i++) {
                        double dv = cand_d[i]; int k = cand_k[i];
                        if (dv < bd || (dv == bd && k < bk)) { bd = dv; bk = k; }
                    }
                    int row = rows_s[r];
                    int oldc = g_code[row];
                    if (bk != oldc) {
                        atomicSub(&g_hist[oldc], 1);
                        atomicAdd(&g_hist[bk], 1);
                        g_code[row] = bk;
                        out_code[row] = (float)bk;
                    }
                }
            } else {
                // single candidate (or overflow fallback): fp32 winner
                if (tid == 0) {
                    int row = rows_s[r];
                    int oldc = g_code[row];
                    if (mi != oldc) {
                        atomicSub(&g_hist[oldc], 1);
                        atomicAdd(&g_hist[mi], 1);
                        g_code[row] = mi;
                        out_code[row] = (float)mi;
                    }
                }
            }
            __syncthreads();
        }
    }

    // ---- last-block ticket: scan hist + compute n ----
    __threadfence();
    if (tid == 0) amlast = (atomicAdd(&g_done, 1) == gridDim.x - 1) ? 1 : 0;
    __syncthreads();
    if (!amlast) return;

    int b0 = g_hist[tid * 4 + 0];
    int b1 = g_hist[tid * 4 + 1];
    int b2 = g_hist[tid * 4 + 2];
    int b3 = g_hist[tid * 4 + 3];
    bsum[tid] = b0 + b1 + b2 + b3;
    __syncthreads();
    for (int off = 1; off < 256; off <<= 1) {
        int v = (tid >= off) ? bsum[tid - off] : 0;
        __syncthreads();
        bsum[tid] += v;
        __syncthreads();
    }
    int excl = bsum[tid] - (b0 + b1 + b2 + b3);
    g_offset[tid * 4 + 0] = excl;
    g_offset[tid * 4 + 1] = excl + b0;
    g_offset[tid * 4 + 2] = excl + b0 + b1;
    g_offset[tid * 4 + 3] = excl + b0 + b1 + b2;
    g_cursor[tid * 4 + 0] = excl;
    g_cursor[tid * 4 + 1] = excl + b0;
    g_cursor[tid * 4 + 2] = excl + b0 + b1;
    g_cursor[tid * 4 + 3] = excl + b0 + b1 + b2;

    float cs = cs_in[tid * 4] + cs_in[tid * 4 + 1] + cs_in[tid * 4 + 2] +
               cs_in[tid * 4 + 3];
    rmin[tid] = cs;
    __syncthreads();
    for (int off = 128; off > 0; off >>= 1) {
        if (tid < off) rmin[tid] += rmin[tid + off];
        __syncthreads();
    }
    if (tid == 0) g_n = DECAY * rmin[0] + (1.0f - DECAY) * (float)N_;
}

// ============================================================
// 5) scatter rows by code
// ============================================================
__global__ void scatter_kernel() {
    int row = blockIdx.x * 1024 + threadIdx.x;
    int c = g_code[row];
    int p = atomicAdd(&g_cursor[c], 1);
    g_rows[p] = row;
}

// ============================================================
// 6) segsum CHUNKED: 1024 blocks x 64 sorted rows each.
// ============================================================
#define CHUNK 64
__global__ __launch_bounds__(128)
void segsum_kernel(const float* __restrict__ in, float* __restrict__ out_q) {
    __shared__ int srow[CHUNK], scode[CHUNK];
    __shared__ float red[128];
    const int t = threadIdx.x;
    const int i0 = blockIdx.x * CHUNK;

    if (t < CHUNK) {
        int r = g_rows[i0 + t];
        srow[t] = r;
        scode[t] = g_code[r];
    }
    __syncthreads();

    float s = 0.0f, dsum = 0.0f;
    int cur = scode[0];
    float ek = g_embT[cur * D_ + t];

    for (int i = 0; i < CHUNK; i++) {
        int c = scode[i];
        if (c != cur) {
            atomicAdd(&g_embSumT[cur * D_ + t], s);
            s = 0.0f;
            cur = c;
            ek = g_embT[cur * D_ + t];
        }
        int row = srow[i];
        float x = in[(size_t)row * D_ + t];
        s += x;
        float df = x - ek;
        dsum = fmaf(df, df, dsum);
        out_q[(size_t)row * D_ + t] = ek;
    }
    atomicAdd(&g_embSumT[cur * D_ + t], s);

    red[t] = dsum;
    __syncthreads();
    for (int off = 64; off > 0; off >>= 1) {
        if (t < off) red[t] += red[t + off];
        __syncthreads();
    }
    if (t == 0) atomicAdd(&g_diff, red[0]);
}

// ============================================================
// 7) finalize: O_CS, O_DIFF, O_MEAN, O_EMB
// ============================================================
__global__ void finalize_kernel(const float* __restrict__ cs_in,
                                const float* __restrict__ mean_in,
                                float* __restrict__ out) {
    int idx = blockIdx.x * blockDim.x + threadIdx.x;
    if (idx < K_)
        out[O_CS + idx] = cs_in[idx] * DECAY + (1.0f - DECAY) * (float)g_hist[idx];
    if (idx == 0)
        out[O_DIFF] = VQ_COMMIT * g_diff / (float)(N_ * D_);
    if (idx >= D_ * K_) return;
    int d = idx >> 10;
    int k = idx & (K_ - 1);
    float em = mean_in[idx] * DECAY + (1.0f - DECAY) * g_embSumT[k * D_ + d];
    out[O_MEAN + idx] = em;
    float n = g_n;
    float ncs = cs_in[k] * DECAY + (1.0f - DECAY) * (float)g_hist[k];
    float cs = (ncs + EPSV) / (n + K_ * EPSV) * n;
    out[O_EMB + idx] = em / cs;
}

// ============================================================
extern "C" void kernel_launch(void* const* d_in, const int* in_sizes, int n_in,
                              void* d_out, int out_size) {
    const float* in      = (const float*)d_in[0];  // [B,T,D]
    const float* emb     = (const float*)d_in[1];  // [D,K]
    const float* cs_in   = (const float*)d_in[2];  // [K]
    const float* mean_in = (const float*)d_in[3];  // [D,K]
    float* out = (float*)d_out;

    static bool attr_set = false;
    if (!attr_set) {
        cudaFuncSetAttribute(argmin_mma_kernel,
                             cudaFuncAttributeMaxDynamicSharedMemorySize,
                             SM_ARG_TOTAL);
        attr_set = true;
    }

    enorm_kernel<<<K_ / 256, 256>>>(emb);                                  // 1
    prep_kernel<<<(K_ * D_) / 256, 256>>>(emb);                            // 2
    argmin_mma_kernel<<<N_ / 128, 256, SM_ARG_TOTAL>>>(in, out + O_CODE);  // 3
    repair_kernel<<<512, 256>>>(in, emb, cs_in, out + O_CODE);             // 4 (ncu slot)
    scatter_kernel<<<N_ / 1024, 1024>>>();                                 // 5
    segsum_kernel<<<N_ / CHUNK, 128>>>(in, out + O_Q);                     // 6
    finalize_kernel<<<(D_ * K_ + 255) / 256, 256>>>(cs_in, mean_in, out);  // 7
}

// round 14
// speedup vs baseline: 3.8867x; 1.0778x over previous
#include <cuda_runtime.h>
#include <cuda_fp16.h>
#include <cstdint>

// Problem constants
#define D_   128
#define K_   1024
#define N_   65536            // B*T = 16*4096
#define DECAY 0.99f
#define EPSV  1e-5f
#define VQ_COMMIT 0.25f
#define REPAIR_THRESH  0.04f
#define CAND_MARGIN    2e-3f
#define MAXCAND 32

// Output layout (floats), concatenated in reference return order
#define O_Q     0
#define O_DIFF  8388608
#define O_CODE  8388609
#define O_EMB   8454145
#define O_CS    8585217
#define O_MEAN  8586241

// -------- device scratch --------
__device__ float g_embT[K_ * D_];          // embedding transposed [K][D]
__device__ float g_enorm[K_];              // ||e_k||^2
__device__ int   g_code[N_];
__device__ float g_embSumT[K_ * D_];       // per-code x-sum, [K][D]
__device__ float g_diff;
__device__ float g_n;
__device__ int   g_nrepair;
__device__ int   g_repair[N_];
__device__ int   g_hist[K_];
__device__ int   g_offset[K_];
__device__ int   g_cursor[K_];
__device__ int   g_rows[N_];
__device__ int   g_done;
// swizzled fp16 codebook image: 8 tiles of [128 codes][128 dims]
__device__ uint16_t g_Eimg[K_ * D_];

// ---------------- helpers ----------------
__device__ __forceinline__ uint32_t smem_u32(const void* p) {
    uint32_t a;
    asm("{ .reg .u64 t; cvta.to.shared.u64 t, %1; cvt.u32.u64 %0, t; }"
        : "=r"(a) : "l"(p));
    return a;
}
__device__ __forceinline__ void ldmx4(uint32_t* r, uint32_t addr) {
    asm volatile("ldmatrix.sync.aligned.m8n8.x4.shared.b16 {%0,%1,%2,%3}, [%4];"
                 : "=r"(r[0]), "=r"(r[1]), "=r"(r[2]), "=r"(r[3]) : "r"(addr));
}
__device__ __forceinline__ void mma16816(float* c, const uint32_t* a,
                                         const uint32_t* b) {
    asm volatile(
        "mma.sync.aligned.m16n8k16.row.col.f32.f16.f16.f32 "
        "{%0,%1,%2,%3}, {%4,%5,%6,%7}, {%8,%9}, {%0,%1,%2,%3};"
        : "+f"(c[0]), "+f"(c[1]), "+f"(c[2]), "+f"(c[3])
        : "r"(a[0]), "r"(a[1]), "r"(a[2]), "r"(a[3]), "r"(b[0]), "r"(b[1]));
}
#define CP16(dst, src) \
    asm volatile("cp.async.ca.shared.global [%0], [%1], 16;" \
                 :: "r"(dst), "l"(src))
#define CP_COMMIT() asm volatile("cp.async.commit_group;" ::: "memory")
#define CP_WAIT0()  asm volatile("cp.async.wait_group 0;" ::: "memory")

__device__ __forceinline__ uint32_t swoff(int r, int ch) {
    return (uint32_t)r * 256u + (uint32_t)((ch ^ (r & 7)) << 4);
}

// merge (b1,b2,i1) with candidate (nb1,nb2,ni)
__device__ __forceinline__ void merge3(float& b1, float& b2, int& i1,
                                       float nb1, float nb2, int ni) {
    if (nb1 < b1 || (nb1 == b1 && ni < i1)) {
        b2 = fminf(b1, nb2);
        b1 = nb1; i1 = ni;
    } else {
        b2 = fminf(b2, nb1);
    }
}

// ============================================================
// 1) zero scratch
// ============================================================
__global__ void zero_kernel() {
    int idx = blockIdx.x * blockDim.x + threadIdx.x;   // K_*D_
    g_embSumT[idx] = 0.0f;
    if (idx < K_) g_hist[idx] = 0;
    if (idx == 0) { g_diff = 0.0f; g_nrepair = 0; g_done = 0; }
}

// ============================================================
// 2) enorm
// ============================================================
__global__ void enorm_kernel(const float* __restrict__ E) {
    int k = blockIdx.x * blockDim.x + threadIdx.x;
    if (k >= K_) return;
    float s = 0.0f;
#pragma unroll 8
    for (int d = 0; d < D_; d++) {
        float v = E[d * K_ + k];
        s = fmaf(v, v, s);
    }
    g_enorm[k] = s;
}

// ============================================================
// 3) prep: fp16 image + embT
// ============================================================
__global__ void prep_kernel(const float* __restrict__ E) {
    int idx = blockIdx.x * blockDim.x + threadIdx.x;   // 131072 = K_*D_
    int k = idx & (K_ - 1);
    int d = idx >> 10;
    float v = E[d * K_ + k];
    __half h = __float2half_rn(v);
    int tile = k >> 7, r = k & 127;
    g_Eimg[tile * 16384 + r * 128 + (((d >> 3) ^ (r & 7)) << 3) + (d & 7)] =
        __half_as_ushort(h);
    g_embT[k * D_ + d] = v;
}

// ============================================================
// 4) argmin via mma.sync fp16 2-term split GEMM (+ hist count)
//    M=64 rows/CTA -> 103KB smem -> 2 CTAs/SM.
//    8 warps = 2 (m32) x 4 (n32).
// ============================================================
#define SM_XH   0
#define SM_XL   16384
#define SM_E0   32768
#define SM_E1   65536
#define SM_ENS  98304
#define SM_CAND 102400
#define SM_ARG_TOTAL (102400 + 3072)

__device__ __forceinline__ void cp_tile(uint32_t dst, int tile, int tid) {
    const char* src = (const char*)g_Eimg + (size_t)tile * 32768;
#pragma unroll
    for (int i = 0; i < 8; i++)
        CP16(dst + tid * 16 + i * 4096, src + tid * 16 + i * 4096);
}

__global__ __launch_bounds__(256, 2)
void argmin_mma_kernel(const float* __restrict__ in, float* __restrict__ out_code) {
    extern __shared__ char smem[];
    const uint32_t sb = smem_u32(smem);
    const int tid = threadIdx.x;
    const int lane = tid & 31;
    const int wid = tid >> 5;
    const int warp_m = wid & 1;      // 2 x m32
    const int warp_q = wid >> 1;     // 4 x n32
    const int row0 = blockIdx.x * 64;

    cp_tile(sb + SM_E0, 0, tid);
    CP_COMMIT();

    float* ens = (float*)(smem + SM_ENS);
#pragma unroll
    for (int i = 0; i < 4; i++) ens[tid + i * 256] = g_enorm[tid + i * 256];

    // build X hi/lo fp16 swizzled images (64 rows)
    {
        const int s = tid & 63;          // dim-pair
        const int rq = tid >> 6;         // row quarter (0..3)
        const float2* gin = (const float2*)in;
#pragma unroll 4
        for (int rr = 0; rr < 16; rr++) {
            int r = rq * 16 + rr;
            float2 x = gin[(size_t)(row0 + r) * 64 + s];
            __half h0 = __float2half_rn(x.x);
            __half h1 = __float2half_rn(x.y);
            __half l0 = __float2half_rn(x.x - __half2float(h0));
            __half l1 = __float2half_rn(x.y - __half2float(h1));
            uint32_t off = (uint32_t)r * 256u +
                           (uint32_t)((((s >> 2) ^ (r & 7)) << 4) + (s & 3) * 4);
            *(uint32_t*)(smem + SM_XH + off) =
                (uint32_t)__half_as_ushort(h0) | ((uint32_t)__half_as_ushort(h1) << 16);
            *(uint32_t*)(smem + SM_XL + off) =
                (uint32_t)__half_as_ushort(l0) | ((uint32_t)__half_as_ushort(l1) << 16);
        }
    }

    const int a_row = lane & 15;
    const int a_ksel = lane >> 4;
    const int b_n = (lane & 7) + ((lane & 16) >> 1);
    const int b_ksel = (lane >> 3) & 1;

    float best[2][2], best2[2][2];
    int bidx[2][2];
#pragma unroll
    for (int mt = 0; mt < 2; mt++)
#pragma unroll
        for (int h = 0; h < 2; h++) {
            best[mt][h] = 3.4e38f; best2[mt][h] = 3.4e38f; bidx[mt][h] = 0;
        }

    for (int nt = 0; nt < 8; nt++) {
        CP_WAIT0();
        __syncthreads();
        if (nt < 7) { cp_tile(sb + (((nt + 1) & 1) ? SM_E1 : SM_E0), nt + 1, tid); CP_COMMIT(); }
        const uint32_t eb = sb + ((nt & 1) ? SM_E1 : SM_E0);

        float acc[2][4][4];
#pragma unroll
        for (int mt = 0; mt < 2; mt++)
#pragma unroll
            for (int nn = 0; nn < 4; nn++)
#pragma unroll
                for (int i = 0; i < 4; i++) acc[mt][nn][i] = 0.0f;

#pragma unroll
        for (int kc = 0; kc < 8; kc++) {
            uint32_t Ah[2][4], Al[2][4];
#pragma unroll
            for (int mt = 0; mt < 2; mt++) {
                int r = warp_m * 32 + mt * 16 + a_row;
                uint32_t off = swoff(r, 2 * kc + a_ksel);
                ldmx4(Ah[mt], sb + SM_XH + off);
                ldmx4(Al[mt], sb + SM_XL + off);
            }
#pragma unroll
            for (int g = 0; g < 2; g++) {
                int n = warp_q * 32 + g * 16 + b_n;
                uint32_t off = swoff(n, 2 * kc + b_ksel);
                uint32_t Bh[4];
                ldmx4(Bh, eb + off);
#pragma unroll
                for (int mt = 0; mt < 2; mt++) {
                    mma16816(acc[mt][2 * g],     Ah[mt], Bh);
                    mma16816(acc[mt][2 * g + 1], Ah[mt], Bh + 2);
                    mma16816(acc[mt][2 * g],     Al[mt], Bh);
                    mma16816(acc[mt][2 * g + 1], Al[mt], Bh + 2);
                }
            }
        }

        const int cbase = nt * 128 + warp_q * 32 + (lane & 3) * 2;
#pragma unroll
        for (int mt = 0; mt < 2; mt++)
#pragma unroll
            for (int nn = 0; nn < 4; nn++)
#pragma unroll
                for (int i = 0; i < 4; i++) {
                    int c = cbase + nn * 8 + (i & 1);
                    int h = i >> 1;
                    float dist = fmaf(-2.0f, acc[mt][nn][i], ens[c]);
                    if (dist < best[mt][h]) {
                        best2[mt][h] = best[mt][h];
                        best[mt][h] = dist; bidx[mt][h] = c;
                    } else {
                        best2[mt][h] = fminf(best2[mt][h], dist);
                    }
                }
    }

    float* cb  = (float*)(smem + SM_CAND);          // [4][64]
    float* cb2 = (float*)(smem + SM_CAND + 1024);
    int*   ci  = (int*)(smem + SM_CAND + 2048);
#pragma unroll
    for (int mt = 0; mt < 2; mt++)
#pragma unroll
        for (int h = 0; h < 2; h++) {
            float b1 = best[mt][h], b2 = best2[mt][h];
            int i1 = bidx[mt][h];
#pragma unroll
            for (int off = 1; off <= 2; off <<= 1) {
                float ob1 = __shfl_xor_sync(0xffffffffu, b1, off);
                int   oi1 = __shfl_xor_sync(0xffffffffu, i1, off);
                float ob2 = __shfl_xor_sync(0xffffffffu, b2, off);
                merge3(b1, b2, i1, ob1, ob2, oi1);
            }
            if ((lane & 3) == 0) {
                int lrow = warp_m * 32 + mt * 16 + (lane >> 2) + 8 * h;
                cb[warp_q * 64 + lrow] = b1;
                cb2[warp_q * 64 + lrow] = b2;
                ci[warp_q * 64 + lrow] = i1;
            }
        }
    __syncthreads();

    if (tid < 64) {
        float fb = cb[tid], fs = cb2[tid];
        int fi = ci[tid];
#pragma unroll
        for (int q = 1; q < 4; q++)
            merge3(fb, fs, fi, cb[q * 64 + tid], cb2[q * 64 + tid],
                   ci[q * 64 + tid]);
        int row = row0 + tid;
        g_code[row] = fi;
        out_code[row] = (float)fi;
        atomicAdd(&g_hist[fi], 1);
        if (fs - fb < REPAIR_THRESH) {
            int slot = atomicAdd(&g_nrepair, 1);
            if (slot < N_) g_repair[slot] = row;
        }
    }
}

// ============================================================
// 5) repair: fp32 full re-rank with dist matrix in smem;
//    fp64 only on candidates within CAND_MARGIN of the min.
//    Last block scans hist + computes n.
// ============================================================
#define RGROUP 8
__global__ __launch_bounds__(256)
void repair_kernel(const float* __restrict__ in,
                   const float* __restrict__ E,
                   const float* __restrict__ cs_in,
                   float* __restrict__ out_code) {
    __shared__ float dists[RGROUP][K_];   // 32 KB
    __shared__ float xs[RGROUP][D_];      // 4 KB
    __shared__ int rows_s[RGROUP];
    __shared__ float rmin[256];
    __shared__ int rmini[256];
    __shared__ int cand_k[MAXCAND];
    __shared__ double cand_d[MAXCAND];
    __shared__ int ncand;
    __shared__ int bsum[256];
    __shared__ int amlast;
    const int tid = threadIdx.x;
    int nrep = g_nrepair;
    if (nrep > N_) nrep = N_;

    for (int base = blockIdx.x * RGROUP; base < nrep; base += gridDim.x * RGROUP) {
        int nr = nrep - base; if (nr > RGROUP) nr = RGROUP;
        if (tid < nr) rows_s[tid] = g_repair[base + tid];
        __syncthreads();
        for (int j = tid; j < nr * D_; j += 256)
            xs[j >> 7][j & 127] = in[(size_t)rows_s[j >> 7] * D_ + (j & 127)];
        __syncthreads();

        // fp32 exact-form distances for all 1024 codes
#pragma unroll
        for (int kk = 0; kk < 4; kk++) {
            int k = tid + kk * 256;
            float s[RGROUP];
#pragma unroll
            for (int r = 0; r < RGROUP; r++) s[r] = 0.0f;
#pragma unroll 4
            for (int d = 0; d < D_; d += 2) {
                float e0 = E[d * K_ + k];
                float e1 = E[(d + 1) * K_ + k];
#pragma unroll
                for (int r = 0; r < RGROUP; r++) {
                    float d0 = xs[r][d] - e0;
                    float d1 = xs[r][d + 1] - e1;
                    s[r] = fmaf(d0, d0, s[r]);
                    s[r] = fmaf(d1, d1, s[r]);
                }
            }
#pragma unroll
            for (int r = 0; r < RGROUP; r++) dists[r][k] = s[r];
        }
        __syncthreads();

        for (int r = 0; r < nr; r++) {
            // block argmin over dists[r][*]
            float b = 3.4e38f; int bi = 0;
#pragma unroll
            for (int kk = 0; kk < 4; kk++) {
                int k = tid + kk * 256;
                float v = dists[r][k];
                if (v < b || (v == b && k < bi)) { b = v; bi = k; }
            }
            rmin[tid] = b; rmini[tid] = bi;
            if (tid == 0) ncand = 0;
            __syncthreads();
            for (int off = 128; off > 0; off >>= 1) {
                if (tid < off) {
                    float ob = rmin[tid + off];
                    int oi = rmini[tid + off];
                    if (ob < rmin[tid] || (ob == rmin[tid] && oi < rmini[tid])) {
                        rmin[tid] = ob; rmini[tid] = oi;
                    }
                }
                __syncthreads();
            }
            float m = rmin[0];
            int mi = rmini[0];
            __syncthreads();

            // gather candidates within margin
#pragma unroll
            for (int kk = 0; kk < 4; kk++) {
                int k = tid + kk * 256;
                if (dists[r][k] < m + CAND_MARGIN) {
                    int p = atomicAdd(&ncand, 1);
                    if (p < MAXCAND) cand_k[p] = k;
                }
            }
            __syncthreads();
            int nc = ncand;

            if (nc > 1 && nc <= MAXCAND) {
                // fp64 exact on candidates (one thread each, 4-way ILP)
                if (tid < nc) {
                    int k = cand_k[tid];
                    double s0 = 0.0, s1 = 0.0, s2 = 0.0, s3 = 0.0;
#pragma unroll 2
                    for (int d = 0; d < D_; d += 4) {
                        double f0 = (double)xs[r][d]     - (double)E[d * K_ + k];
                        double f1 = (double)xs[r][d + 1] - (double)E[(d + 1) * K_ + k];
                        double f2 = (double)xs[r][d + 2] - (double)E[(d + 2) * K_ + k];
                        double f3 = (double)xs[r][d + 3] - (double)E[(d + 3) * K_ + k];
                        s0 = fma(f0, f0, s0);
                        s1 = fma(f1, f1, s1);
                        s2 = fma(f2, f2, s2);
                        s3 = fma(f3, f3, s3);
                    }
                    cand_d[tid] = (s0 + s1) + (s2 + s3);
                }
                __syncthreads();
                if (tid == 0) {
                    double bd = 1e300; int bk = 1 << 30;
                    for (int i = 0; i < nc; i++) {
                        double dv = cand_d[i]; int k = cand_k[i];
                        if (dv < bd || (dv == bd && k < bk)) { bd = dv; bk = k; }
                    }
                    int row = rows_s[r];
                    int oldc = g_code[row];
                    if (bk != oldc) {
                        atomicSub(&g_hist[oldc], 1);
                        atomicAdd(&g_hist[bk], 1);
                        g_code[row] = bk;
                        out_code[row] = (float)bk;
                    }
                }
            } else {
                // single candidate (or overflow fallback): fp32 winner
                if (tid == 0) {
                    int row = rows_s[r];
                    int oldc = g_code[row];
                    if (mi != oldc) {
                        atomicSub(&g_hist[oldc], 1);
                        atomicAdd(&g_hist[mi], 1);
                        g_code[row] = mi;
                        out_code[row] = (float)mi;
                    }
                }
            }
            __syncthreads();
        }
    }

    // ---- last-block ticket: scan hist + compute n ----
    __threadfence();
    if (tid == 0) amlast = (atomicAdd(&g_done, 1) == gridDim.x - 1) ? 1 : 0;
    __syncthreads();
    if (!amlast) return;

    int b0 = g_hist[tid * 4 + 0];
    int b1 = g_hist[tid * 4 + 1];
    int b2 = g_hist[tid * 4 + 2];
    int b3 = g_hist[tid * 4 + 3];
    bsum[tid] = b0 + b1 + b2 + b3;
    __syncthreads();
    for (int off = 1; off < 256; off <<= 1) {
        int v = (tid >= off) ? bsum[tid - off] : 0;
        __syncthreads();
        bsum[tid] += v;
        __syncthreads();
    }
    int excl = bsum[tid] - (b0 + b1 + b2 + b3);
    g_offset[tid * 4 + 0] = excl;
    g_offset[tid * 4 + 1] = excl + b0;
    g_offset[tid * 4 + 2] = excl + b0 + b1;
    g_offset[tid * 4 + 3] = excl + b0 + b1 + b2;
    g_cursor[tid * 4 + 0] = excl;
    g_cursor[tid * 4 + 1] = excl + b0;
    g_cursor[tid * 4 + 2] = excl + b0 + b1;
    g_cursor[tid * 4 + 3] = excl + b0 + b1 + b2;

    float cs = cs_in[tid * 4] + cs_in[tid * 4 + 1] + cs_in[tid * 4 + 2] +
               cs_in[tid * 4 + 3];
    rmin[tid] = cs;
    __syncthreads();
    for (int off = 128; off > 0; off >>= 1) {
        if (tid < off) rmin[tid] += rmin[tid + off];
        __syncthreads();
    }
    if (tid == 0) g_n = DECAY * rmin[0] + (1.0f - DECAY) * (float)N_;
}

// ============================================================
// 6) scatter rows by code
// ============================================================
__global__ void scatter_kernel() {
    int row = blockIdx.x * 1024 + threadIdx.x;
    int c = g_code[row];
    int p = atomicAdd(&g_cursor[c], 1);
    g_rows[p] = row;
}

// ============================================================
// 7) segsum CHUNKED: 1024 blocks x 64 sorted rows each.
// ============================================================
#define CHUNK 64
__global__ __launch_bounds__(128)
void segsum_kernel(const float* __restrict__ in, float* __restrict__ out_q) {
    __shared__ int srow[CHUNK], scode[CHUNK];
    __shared__ float red[128];
    const int t = threadIdx.x;
    const int i0 = blockIdx.x * CHUNK;

    if (t < CHUNK) {
        int r = g_rows[i0 + t];
        srow[t] = r;
        scode[t] = g_code[r];
    }
    __syncthreads();

    float s = 0.0f, dsum = 0.0f;
    int cur = scode[0];
    float ek = g_embT[cur * D_ + t];

    for (int i = 0; i < CHUNK; i++) {
        int c = scode[i];
        if (c != cur) {
            atomicAdd(&g_embSumT[cur * D_ + t], s);
            s = 0.0f;
            cur = c;
            ek = g_embT[cur * D_ + t];
        }
        int row = srow[i];
        float x = in[(size_t)row * D_ + t];
        s += x;
        float df = x - ek;
        dsum = fmaf(df, df, dsum);
        out_q[(size_t)row * D_ + t] = ek;
    }
    atomicAdd(&g_embSumT[cur * D_ + t], s);

    red[t] = dsum;
    __syncthreads();
    for (int off = 64; off > 0; off >>= 1) {
        if (t < off) red[t] += red[t + off];
        __syncthreads();
    }
    if (t == 0) atomicAdd(&g_diff, red[0]);
}

// ============================================================
// 8) finalize: O_CS, O_DIFF, O_MEAN, O_EMB
// ============================================================
__global__ void finalize_kernel(const float* __restrict__ cs_in,
                                const float* __restrict__ mean_in,
                                float* __restrict__ out) {
    int idx = blockIdx.x * blockDim.x + threadIdx.x;
    if (idx < K_)
        out[O_CS + idx] = cs_in[idx] * DECAY + (1.0f - DECAY) * (float)g_hist[idx];
    if (idx == 0)
        out[O_DIFF] = VQ_COMMIT * g_diff / (float)(N_ * D_);
    if (idx >= D_ * K_) return;
    int d = idx >> 10;
    int k = idx & (K_ - 1);
    float em = mean_in[idx] * DECAY + (1.0f - DECAY) * g_embSumT[k * D_ + d];
    out[O_MEAN + idx] = em;
    float n = g_n;
    float ncs = cs_in[k] * DECAY + (1.0f - DECAY) * (float)g_hist[k];
    float cs = (ncs + EPSV) / (n + K_ * EPSV) * n;
    out[O_EMB + idx] = em / cs;
}

// ============================================================
extern "C" void kernel_launch(void* const* d_in, const int* in_sizes, int n_in,
                              void* d_out, int out_size) {
    const float* in      = (const float*)d_in[0];  // [B,T,D]
    const float* emb     = (const float*)d_in[1];  // [D,K]
    const float* cs_in   = (const float*)d_in[2];  // [K]
    const float* mean_in = (const float*)d_in[3];  // [D,K]
    float* out = (float*)d_out;

    static bool attr_set = false;
    if (!attr_set) {
        cudaFuncSetAttribute(argmin_mma_kernel,
                             cudaFuncAttributeMaxDynamicSharedMemorySize,
                             SM_ARG_TOTAL);
        attr_set = true;
    }

    zero_kernel<<<(K_ * D_) / 256, 256>>>();                               // 1
    enorm_kernel<<<K_ / 256, 256>>>(emb);                                  // 2
    prep_kernel<<<(K_ * D_) / 256, 256>>>(emb);                            // 3
    argmin_mma_kernel<<<N_ / 64, 256, SM_ARG_TOTAL>>>(in, out + O_CODE);   // 4 (ncu slot)
    repair_kernel<<<512, 256>>>(in, emb, cs_in, out + O_CODE);             // 5
    scatter_kernel<<<N_ / 1024, 1024>>>();                                 // 6
    segsum_kernel<<<N_ / CHUNK, 128>>>(in, out + O_Q);                     // 7
    finalize_kernel<<<(D_ * K_ + 255) / 256, 256>>>(cs_in, mean_in, out);  // 8
}

// round 15
// speedup vs baseline: 3.8945x; 1.0020x over previous
#include <cuda_runtime.h>
#include <cuda_fp16.h>
#include <cstdint>

// Problem constants
#define D_   128
#define K_   1024
#define N_   65536            // B*T = 16*4096
#define DECAY 0.99f
#define EPSV  1e-5f
#define VQ_COMMIT 0.25f
#define REPAIR_THRESH  0.04f
#define CAND_MARGIN    2e-3f
#define MAXCAND 32

// Output layout (floats), concatenated in reference return order
#define O_Q     0
#define O_DIFF  8388608
#define O_CODE  8388609
#define O_EMB   8454145
#define O_CS    8585217
#define O_MEAN  8586241

// -------- device scratch --------
__device__ float g_embT[K_ * D_];          // embedding transposed [K][D]
__device__ float g_enorm[K_];              // ||e_k||^2
__device__ uint32_t g_enormH2[K_];         // packed half2(hi,lo) of ||e_k||^2
__device__ int   g_code[N_];
__device__ float g_embSumT[K_ * D_];       // per-code x-sum, [K][D]
__device__ float g_diff;
__device__ float g_n;
__device__ int   g_nrepair;
__device__ int   g_repair[N_];
__device__ int   g_hist[K_];
__device__ int   g_offset[K_];
__device__ int   g_cursor[K_];
__device__ int   g_rows[N_];
__device__ int   g_done;
// swizzled fp16 image of (-2*E): 8 tiles of [128 codes][128 dims]
__device__ uint16_t g_Eimg[K_ * D_];

// ---------------- helpers ----------------
__device__ __forceinline__ uint32_t smem_u32(const void* p) {
    uint32_t a;
    asm("{ .reg .u64 t; cvta.to.shared.u64 t, %1; cvt.u32.u64 %0, t; }"
        : "=r"(a) : "l"(p));
    return a;
}
__device__ __forceinline__ void ldmx4(uint32_t* r, uint32_t addr) {
    asm volatile("ldmatrix.sync.aligned.m8n8.x4.shared.b16 {%0,%1,%2,%3}, [%4];"
                 : "=r"(r[0]), "=r"(r[1]), "=r"(r[2]), "=r"(r[3]) : "r"(addr));
}
__device__ __forceinline__ void mma16816(float* c, const uint32_t* a,
                                         const uint32_t* b) {
    asm volatile(
        "mma.sync.aligned.m16n8k16.row.col.f32.f16.f16.f32 "
        "{%0,%1,%2,%3}, {%4,%5,%6,%7}, {%8,%9}, {%0,%1,%2,%3};"
        : "+f"(c[0]), "+f"(c[1]), "+f"(c[2]), "+f"(c[3])
        : "r"(a[0]), "r"(a[1]), "r"(a[2]), "r"(a[3]), "r"(b[0]), "r"(b[1]));
}
#define CP16(dst, src) \
    asm volatile("cp.async.ca.shared.global [%0], [%1], 16;" \
                 :: "r"(dst), "l"(src))
#define CP_COMMIT() asm volatile("cp.async.commit_group;" ::: "memory")
#define CP_WAIT0()  asm volatile("cp.async.wait_group 0;" ::: "memory")

__device__ __forceinline__ uint32_t swoff(int r, int ch) {
    return (uint32_t)r * 256u + (uint32_t)((ch ^ (r & 7)) << 4);
}

// merge (b1,b2,i1) with candidate (nb1,nb2,ni)
__device__ __forceinline__ void merge3(float& b1, float& b2, int& i1,
                                       float nb1, float nb2, int ni) {
    if (nb1 < b1 || (nb1 == b1 && ni < i1)) {
        b2 = fminf(b1, nb2);
        b1 = nb1; i1 = ni;
    } else {
        b2 = fminf(b2, nb1);
    }
}

// ============================================================
// 1) zero scratch
// ============================================================
__global__ void zero_kernel() {
    int idx = blockIdx.x * blockDim.x + threadIdx.x;   // K_*D_
    g_embSumT[idx] = 0.0f;
    if (idx < K_) g_hist[idx] = 0;
    if (idx == 0) { g_diff = 0.0f; g_nrepair = 0; g_done = 0; }
}

// ============================================================
// 2) enorm (+ packed half2 hi/lo for the MMA enorm chunk)
// ============================================================
__global__ void enorm_kernel(const float* __restrict__ E) {
    int k = blockIdx.x * blockDim.x + threadIdx.x;
    if (k >= K_) return;
    float s = 0.0f;
#pragma unroll 8
    for (int d = 0; d < D_; d++) {
        float v = E[d * K_ + k];
        s = fmaf(v, v, s);
    }
    g_enorm[k] = s;
    __half h = __float2half_rn(s);
    __half l = __float2half_rn(s - __half2float(h));
    g_enormH2[k] = (uint32_t)__half_as_ushort(h) |
                   ((uint32_t)__half_as_ushort(l) << 16);
}

// ============================================================
// 3) prep: fp16 image of (-2E) + embT
// ============================================================
__global__ void prep_kernel(const float* __restrict__ E) {
    int idx = blockIdx.x * blockDim.x + threadIdx.x;   // 131072 = K_*D_
    int k = idx & (K_ - 1);
    int d = idx >> 10;
    float v = E[d * K_ + k];
    __half h = __float2half_rn(-2.0f * v);
    int tile = k >> 7, r = k & 127;
    g_Eimg[tile * 16384 + r * 128 + (((d >> 3) ^ (r & 7)) << 3) + (d & 7)] =
        __half_as_ushort(h);
    g_embT[k * D_ + d] = v;
}

// ============================================================
// 4) argmin via mma.sync fp16 2-term split GEMM, with ||e||^2
//    folded into the MMA via a constant-ones A fragment.
//    M=64 rows/CTA -> 2 CTAs/SM. 8 warps = 2 (m32) x 4 (n32).
// ============================================================
#define SM_XH   0
#define SM_XL   16384
#define SM_E0   32768
#define SM_E1   65536
#define SM_ENS  98304
#define SM_CAND 102400
#define SM_ARG_TOTAL (102400 + 3072)

__device__ __forceinline__ void cp_tile(uint32_t dst, int tile, int tid) {
    const char* src = (const char*)g_Eimg + (size_t)tile * 32768;
#pragma unroll
    for (int i = 0; i < 8; i++)
        CP16(dst + tid * 16 + i * 4096, src + tid * 16 + i * 4096);
}

__global__ __launch_bounds__(256, 2)
void argmin_mma_kernel(const float* __restrict__ in, float* __restrict__ out_code) {
    extern __shared__ char smem[];
    const uint32_t sb = smem_u32(smem);
    const int tid = threadIdx.x;
    const int lane = tid & 31;
    const int wid = tid >> 5;
    const int warp_m = wid & 1;      // 2 x m32
    const int warp_q = wid >> 1;     // 4 x n32
    const int row0 = blockIdx.x * 64;

    cp_tile(sb + SM_E0, 0, tid);
    CP_COMMIT();

    uint32_t* ensp = (uint32_t*)(smem + SM_ENS);
#pragma unroll
    for (int i = 0; i < 4; i++) ensp[tid + i * 256] = g_enormH2[tid + i * 256];

    // build X hi/lo fp16 swizzled images (64 rows)
    {
        const int s = tid & 63;          // dim-pair
        const int rq = tid >> 6;         // row quarter (0..3)
        const float2* gin = (const float2*)in;
#pragma unroll 4
        for (int rr = 0; rr < 16; rr++) {
            int r = rq * 16 + rr;
            float2 x = gin[(size_t)(row0 + r) * 64 + s];
            __half h0 = __float2half_rn(x.x);
            __half h1 = __float2half_rn(x.y);
            __half l0 = __float2half_rn(x.x - __half2float(h0));
            __half l1 = __float2half_rn(x.y - __half2float(h1));
            uint32_t off = (uint32_t)r * 256u +
                           (uint32_t)((((s >> 2) ^ (r & 7)) << 4) + (s & 3) * 4);
            *(uint32_t*)(smem + SM_XH + off) =
                (uint32_t)__half_as_ushort(h0) | ((uint32_t)__half_as_ushort(h1) << 16);
            *(uint32_t*)(smem + SM_XL + off) =
                (uint32_t)__half_as_ushort(l0) | ((uint32_t)__half_as_ushort(l1) << 16);
        }
    }

    const int a_row = lane & 15;
    const int a_ksel = lane >> 4;
    const int b_n = (lane & 7) + ((lane & 16) >> 1);
    const int b_ksel = (lane >> 3) & 1;

    float best[2][2], best2[2][2];
    int bidx[2][2];
#pragma unroll
    for (int mt = 0; mt < 2; mt++)
#pragma unroll
        for (int h = 0; h < 2; h++) {
            best[mt][h] = 3.4e38f; best2[mt][h] = 3.4e38f; bidx[mt][h] = 0;
        }

    const uint32_t Aones[4] = {0x3C003C00u, 0x3C003C00u, 0x3C003C00u, 0x3C003C00u};

    for (int nt = 0; nt < 8; nt++) {
        CP_WAIT0();
        __syncthreads();
        if (nt < 7) { cp_tile(sb + (((nt + 1) & 1) ? SM_E1 : SM_E0), nt + 1, tid); CP_COMMIT(); }
        const uint32_t eb = sb + ((nt & 1) ? SM_E1 : SM_E0);

        float acc[2][4][4];
#pragma unroll
        for (int mt = 0; mt < 2; mt++)
#pragma unroll
            for (int nn = 0; nn < 4; nn++)
#pragma unroll
                for (int i = 0; i < 4; i++) acc[mt][nn][i] = 0.0f;

#pragma unroll
        for (int kc = 0; kc < 8; kc++) {
            uint32_t Ah[2][4], Al[2][4];
#pragma unroll
            for (int mt = 0; mt < 2; mt++) {
                int r = warp_m * 32 + mt * 16 + a_row;
                uint32_t off = swoff(r, 2 * kc + a_ksel);
                ldmx4(Ah[mt], sb + SM_XH + off);
                ldmx4(Al[mt], sb + SM_XL + off);
            }
#pragma unroll
            for (int g = 0; g < 2; g++) {
                int n = warp_q * 32 + g * 16 + b_n;
                uint32_t off = swoff(n, 2 * kc + b_ksel);
                uint32_t Bh[4];
                ldmx4(Bh, eb + off);
#pragma unroll
                for (int mt = 0; mt < 2; mt++) {
                    mma16816(acc[mt][2 * g],     Ah[mt], Bh);
                    mma16816(acc[mt][2 * g + 1], Ah[mt], Bh + 2);
                    mma16816(acc[mt][2 * g],     Al[mt], Bh);
                    mma16816(acc[mt][2 * g + 1], Al[mt], Bh + 2);
                }
            }
        }

        // enorm chunk: A = ones, B = [enorm_hi, enorm_lo, 0...] per n-column.
        // m16n8k16 B fragment: b0 holds k=(lane%4)*2,+1 at col n=lane>>2;
        // only lane%4==0 carries k=0,1 -> packed half2(hi,lo). b1 (k=8..) = 0.
#pragma unroll
        for (int g = 0; g < 2; g++)
#pragma unroll
            for (int j = 0; j < 2; j++) {
                uint32_t b0 = 0u;
                if ((lane & 3) == 0)
                    b0 = ensp[nt * 128 + warp_q * 32 + g * 16 + j * 8 + (lane >> 2)];
                uint32_t Bf[2] = {b0, 0u};
                mma16816(acc[0][2 * g + j], Aones, Bf);
                mma16816(acc[1][2 * g + j], Aones, Bf);
            }

        // fold: dist = acc directly (= -2 x.e + ||e||^2)
        const int cbase = nt * 128 + warp_q * 32 + (lane & 3) * 2;
#pragma unroll
        for (int mt = 0; mt < 2; mt++)
#pragma unroll
            for (int nn = 0; nn < 4; nn++)
#pragma unroll
                for (int i = 0; i < 4; i++) {
                    int c = cbase + nn * 8 + (i & 1);
                    int h = i >> 1;
                    float dist = acc[mt][nn][i];
                    if (dist < best[mt][h]) {
                        best2[mt][h] = best[mt][h];
                        best[mt][h] = dist; bidx[mt][h] = c;
                    } else {
                        best2[mt][h] = fminf(best2[mt][h], dist);
                    }
                }
    }

    float* cb  = (float*)(smem + SM_CAND);          // [4][64]
    float* cb2 = (float*)(smem + SM_CAND + 1024);
    int*   ci  = (int*)(smem + SM_CAND + 2048);
#pragma unroll
    for (int mt = 0; mt < 2; mt++)
#pragma unroll
        for (int h = 0; h < 2; h++) {
            float b1 = best[mt][h], b2 = best2[mt][h];
            int i1 = bidx[mt][h];
#pragma unroll
            for (int off = 1; off <= 2; off <<= 1) {
                float ob1 = __shfl_xor_sync(0xffffffffu, b1, off);
                int   oi1 = __shfl_xor_sync(0xffffffffu, i1, off);
                float ob2 = __shfl_xor_sync(0xffffffffu, b2, off);
                merge3(b1, b2, i1, ob1, ob2, oi1);
            }
            if ((lane & 3) == 0) {
                int lrow = warp_m * 32 + mt * 16 + (lane >> 2) + 8 * h;
                cb[warp_q * 64 + lrow] = b1;
                cb2[warp_q * 64 + lrow] = b2;
                ci[warp_q * 64 + lrow] = i1;
            }
        }
    __syncthreads();

    if (tid < 64) {
        float fb = cb[tid], fs = cb2[tid];
        int fi = ci[tid];
#pragma unroll
        for (int q = 1; q < 4; q++)
            merge3(fb, fs, fi, cb[q * 64 + tid], cb2[q * 64 + tid],
                   ci[q * 64 + tid]);
        int row = row0 + tid;
        g_code[row] = fi;
        out_code[row] = (float)fi;
        atomicAdd(&g_hist[fi], 1);
        if (fs - fb < REPAIR_THRESH) {
            int slot = atomicAdd(&g_nrepair, 1);
            if (slot < N_) g_repair[slot] = row;
        }
    }
}

// ============================================================
// 5) repair: fp32 full re-rank with dist matrix in smem;
//    fp64 only on candidates within CAND_MARGIN of the min.
//    Last block scans hist + computes n.
// ============================================================
#define RGROUP 8
__global__ __launch_bounds__(256)
void repair_kernel(const float* __restrict__ in,
                   const float* __restrict__ E,
                   const float* __restrict__ cs_in,
                   float* __restrict__ out_code) {
    __shared__ float dists[RGROUP][K_];   // 32 KB
    __shared__ float xs[RGROUP][D_];      // 4 KB
    __shared__ int rows_s[RGROUP];
    __shared__ float rmin[256];
    __shared__ int rmini[256];
    __shared__ int cand_k[MAXCAND];
    __shared__ double cand_d[MAXCAND];
    __shared__ int ncand;
    __shared__ int bsum[256];
    __shared__ int amlast;
    const int tid = threadIdx.x;
    int nrep = g_nrepair;
    if (nrep > N_) nrep = N_;

    for (int base = blockIdx.x * RGROUP; base < nrep; base += gridDim.x * RGROUP) {
        int nr = nrep - base; if (nr > RGROUP) nr = RGROUP;
        if (tid < nr) rows_s[tid] = g_repair[base + tid];
        __syncthreads();
        for (int j = tid; j < nr * D_; j += 256)
            xs[j >> 7][j & 127] = in[(size_t)rows_s[j >> 7] * D_ + (j & 127)];
        __syncthreads();

        // fp32 exact-form distances for all 1024 codes
#pragma unroll
        for (int kk = 0; kk < 4; kk++) {
            int k = tid + kk * 256;
            float s[RGROUP];
#pragma unroll
            for (int r = 0; r < RGROUP; r++) s[r] = 0.0f;
#pragma unroll 4
            for (int d = 0; d < D_; d += 2) {
                float e0 = E[d * K_ + k];
                float e1 = E[(d + 1) * K_ + k];
#pragma unroll
                for (int r = 0; r < RGROUP; r++) {
                    float d0 = xs[r][d] - e0;
                    float d1 = xs[r][d + 1] - e1;
                    s[r] = fmaf(d0, d0, s[r]);
                    s[r] = fmaf(d1, d1, s[r]);
                }
            }
#pragma unroll
            for (int r = 0; r < RGROUP; r++) dists[r][k] = s[r];
        }
        __syncthreads();

        for (int r = 0; r < nr; r++) {
            // block argmin over dists[r][*]
            float b = 3.4e38f; int bi = 0;
#pragma unroll
            for (int kk = 0; kk < 4; kk++) {
                int k = tid + kk * 256;
                float v = dists[r][k];
                if (v < b || (v == b && k < bi)) { b = v; bi = k; }
            }
            rmin[tid] = b; rmini[tid] = bi;
            if (tid == 0) ncand = 0;
            __syncthreads();
            for (int off = 128; off > 0; off >>= 1) {
                if (tid < off) {
                    float ob = rmin[tid + off];
                    int oi = rmini[tid + off];
                    if (ob < rmin[tid] || (ob == rmin[tid] && oi < rmini[tid])) {
                        rmin[tid] = ob; rmini[tid] = oi;
                    }
                }
                __syncthreads();
            }
            float m = rmin[0];
            int mi = rmini[0];
            __syncthreads();

            // gather candidates within margin
#pragma unroll
            for (int kk = 0; kk < 4; kk++) {
                int k = tid + kk * 256;
                if (dists[r][k] < m + CAND_MARGIN) {
                    int p = atomicAdd(&ncand, 1);
                    if (p < MAXCAND) cand_k[p] = k;
                }
            }
            __syncthreads();
            int nc = ncand;

            if (nc > 1 && nc <= MAXCAND) {
                // fp64 exact on candidates (one thread each, 4-way ILP)
                if (tid < nc) {
                    int k = cand_k[tid];
                    double s0 = 0.0, s1 = 0.0, s2 = 0.0, s3 = 0.0;
#pragma unroll 2
                    for (int d = 0; d < D_; d += 4) {
                        double f0 = (double)xs[r][d]     - (double)E[d * K_ + k];
                        double f1 = (double)xs[r][d + 1] - (double)E[(d + 1) * K_ + k];
                        double f2 = (double)xs[r][d + 2] - (double)E[(d + 2) * K_ + k];
                        double f3 = (double)xs[r][d + 3] - (double)E[(d + 3) * K_ + k];
                        s0 = fma(f0, f0, s0);
                        s1 = fma(f1, f1, s1);
                        s2 = fma(f2, f2, s2);
                        s3 = fma(f3, f3, s3);
                    }
                    cand_d[tid] = (s0 + s1) + (s2 + s3);
                }
                __syncthreads();
                if (tid == 0) {
                    double bd = 1e300; int bk = 1 << 30;
                    for (int i = 0; i < nc; i++) {
                        double dv = cand_d[i]; int k = cand_k[i];
                        if (dv < bd || (dv == bd && k < bk)) { bd = dv; bk = k; }
                    }
                    int row = rows_s[r];
                    int oldc = g_code[row];
                    if (bk != oldc) {
                        atomicSub(&g_hist[oldc], 1);
                        atomicAdd(&g_hist[bk], 1);
                        g_code[row] = bk;
                        out_code[row] = (float)bk;
                    }
                }
            } else {
                // single candidate (or overflow fallback): fp32 winner
                if (tid == 0) {
                    int row = rows_s[r];
                    int oldc = g_code[row];
                    if (mi != oldc) {
                        atomicSub(&g_hist[oldc], 1);
                        atomicAdd(&g_hist[mi], 1);
                        g_code[row] = mi;
                        out_code[row] = (float)mi;
                    }
                }
            }
            __syncthreads();
        }
    }

    // ---- last-block ticket: scan hist + compute n ----
    __threadfence();
    if (tid == 0) amlast = (atomicAdd(&g_done, 1) == gridDim.x - 1) ? 1 : 0;
    __syncthreads();
    if (!amlast) return;

    int b0 = g_hist[tid * 4 + 0];
    int b1 = g_hist[tid * 4 + 1];
    int b2 = g_hist[tid * 4 + 2];
    int b3 = g_hist[tid * 4 + 3];
    bsum[tid] = b0 + b1 + b2 + b3;
    __syncthreads();
    for (int off = 1; off < 256; off <<= 1) {
        int v = (tid >= off) ? bsum[tid - off] : 0;
        __syncthreads();
        bsum[tid] += v;
        __syncthreads();
    }
    int excl = bsum[tid] - (b0 + b1 + b2 + b3);
    g_offset[tid * 4 + 0] = excl;
    g_offset[tid * 4 + 1] = excl + b0;
    g_offset[tid * 4 + 2] = excl + b0 + b1;
    g_offset[tid * 4 + 3] = excl + b0 + b1 + b2;
    g_cursor[tid * 4 + 0] = excl;
    g_cursor[tid * 4 + 1] = excl + b0;
    g_cursor[tid * 4 + 2] = excl + b0 + b1;
    g_cursor[tid * 4 + 3] = excl + b0 + b1 + b2;

    float cs = cs_in[tid * 4] + cs_in[tid * 4 + 1] + cs_in[tid * 4 + 2] +
               cs_in[tid * 4 + 3];
    rmin[tid] = cs;
    __syncthreads();
    for (int off = 128; off > 0; off >>= 1) {
        if (tid < off) rmin[tid] += rmin[tid + off];
        __syncthreads();
    }
    if (tid == 0) g_n = DECAY * rmin[0] + (1.0f - DECAY) * (float)N_;
}

// ============================================================
// 6) scatter rows by code
// ============================================================
__global__ void scatter_kernel() {
    int row = blockIdx.x * 1024 + threadIdx.x;
    int c = g_code[row];
    int p = atomicAdd(&g_cursor[c], 1);
    g_rows[p] = row;
}

// ============================================================
// 7) segsum CHUNKED: 1024 blocks x 64 sorted rows each.
// ============================================================
#define CHUNK 64
__global__ __launch_bounds__(128)
void segsum_kernel(const float* __restrict__ in, float* __restrict__ out_q) {
    __shared__ int srow[CHUNK], scode[CHUNK];
    __shared__ float red[128];
    const int t = threadIdx.x;
    const int i0 = blockIdx.x * CHUNK;

    if (t < CHUNK) {
        int r = g_rows[i0 + t];
        srow[t] = r;
        scode[t] = g_code[r];
    }
    __syncthreads();

    float s = 0.0f, dsum = 0.0f;
    int cur = scode[0];
    float ek = g_embT[cur * D_ + t];

    for (int i = 0; i < CHUNK; i++) {
        int c = scode[i];
        if (c != cur) {
            atomicAdd(&g_embSumT[cur * D_ + t], s);
            s = 0.0f;
            cur = c;
            ek = g_embT[cur * D_ + t];
        }
        int row = srow[i];
        float x = in[(size_t)row * D_ + t];
        s += x;
        float df = x - ek;
        dsum = fmaf(df, df, dsum);
        out_q[(size_t)row * D_ + t] = ek;
    }
    atomicAdd(&g_embSumT[cur * D_ + t], s);

    red[t] = dsum;
    __syncthreads();
    for (int off = 64; off > 0; off >>= 1) {
        if (t < off) red[t] += red[t + off];
        __syncthreads();
    }
    if (t == 0) atomicAdd(&g_diff, red[0]);
}

// ============================================================
// 8) finalize: O_CS, O_DIFF, O_MEAN, O_EMB
// ============================================================
__global__ void finalize_kernel(const float* __restrict__ cs_in,
                                const float* __restrict__ mean_in,
                                float* __restrict__ out) {
    int idx = blockIdx.x * blockDim.x + threadIdx.x;
    if (idx < K_)
        out[O_CS + idx] = cs_in[idx] * DECAY + (1.0f - DECAY) * (float)g_hist[idx];
    if (idx == 0)
        out[O_DIFF] = VQ_COMMIT * g_diff / (float)(N_ * D_);
    if (idx >= D_ * K_) return;
    int d = idx >> 10;
    int k = idx & (K_ - 1);
    float em = mean_in[idx] * DECAY + (1.0f - DECAY) * g_embSumT[k * D_ + d];
    out[O_MEAN + idx] = em;
    float n = g_n;
    float ncs = cs_in[k] * DECAY + (1.0f - DECAY) * (float)g_hist[k];
    float cs = (ncs + EPSV) / (n + K_ * EPSV) * n;
    out[O_EMB + idx] = em / cs;
}

// ============================================================
extern "C" void kernel_launch(void* const* d_in, const int* in_sizes, int n_in,
                              void* d_out, int out_size) {
    const float* in      = (const float*)d_in[0];  // [B,T,D]
    const float* emb     = (const float*)d_in[1];  // [D,K]
    const float* cs_in   = (const float*)d_in[2];  // [K]
    const float* mean_in = (const float*)d_in[3];  // [D,K]
    float* out = (float*)d_out;

    static bool attr_set = false;
    if (!attr_set) {
        cudaFuncSetAttribute(argmin_mma_kernel,
                             cudaFuncAttributeMaxDynamicSharedMemorySize,
                             SM_ARG_TOTAL);
        attr_set = true;
    }

    zero_kernel<<<(K_ * D_) / 256, 256>>>();                               // 1
    enorm_kernel<<<K_ / 256, 256>>>(emb);                                  // 2
    prep_kernel<<<(K_ * D_) / 256, 256>>>(emb);                            // 3
    argmin_mma_kernel<<<N_ / 64, 256, SM_ARG_TOTAL>>>(in, out + O_CODE);   // 4 (ncu slot)
    repair_kernel<<<512, 256>>>(in, emb, cs_in, out + O_CODE);             // 5
    scatter_kernel<<<N_ / 1024, 1024>>>();                                 // 6
    segsum_kernel<<<N_ / CHUNK, 128>>>(in, out + O_Q);                     // 7
    finalize_kernel<<<(D_ * K_ + 255) / 256, 256>>>(cs_in, mean_in, out);  // 8
}